// round 1
// baseline (speedup 1.0000x reference)
#include <cuda_runtime.h>

// Problem constants (match reference module)
namespace {
constexpr int kB = 32, kT = 200, kR = 4096, kC = 81;
constexpr float kIouTh = 0.7f;
constexpr int kThreads = 256;
constexpr int kIlp = 4;
constexpr int kRPerBlock = kThreads * kIlp;     // 1024
constexpr int kBlocksPerB = kR / kRPerBlock;    // 4
constexpr int kNBlocks = kB * kBlocksPerB;      // 128
}

// Per-block partials: [npos, ce_sum, acc_sum, sl1_sum]
__device__ float g_partials[kNBlocks][4];

__device__ __forceinline__ float warp_sum(float v) {
#pragma unroll
    for (int o = 16; o > 0; o >>= 1) v += __shfl_down_sync(0xffffffffu, v, o);
    return v;
}

__global__ __launch_bounds__(kThreads) void rcnn_main(
    const float4* __restrict__ nms_reg,   // [B,R,4]
    const float4* __restrict__ rcnn_reg,  // [B,R,4]
    const float*  __restrict__ rcnn_cls,  // [B,R,C]
    const float4* __restrict__ bboxes,    // [B,T,4]
    const int*    __restrict__ classes)   // [B,T]
{
    __shared__ float4 s_box[kT];
    __shared__ float  s_area[kT];
    __shared__ int    s_cls[kT];

    const int b = blockIdx.x / kBlocksPerB;
    const int chunk = blockIdx.x % kBlocksPerB;
    const int tid = threadIdx.x;

    for (int i = tid; i < kT; i += kThreads) {
        float4 bb = bboxes[b * kT + i];
        s_box[i] = bb;
        s_area[i] = (bb.z - bb.x) * (bb.w - bb.y);
        s_cls[i] = classes[b * kT + i];
    }
    __syncthreads();

    float4 a[kIlp];
    float  areaA[kIlp];
    float  binter[kIlp], bden[kIlp];
    int    bidx[kIlp];

#pragma unroll
    for (int i = 0; i < kIlp; i++) {
        int r = chunk * kRPerBlock + i * kThreads + tid;   // coalesced
        a[i] = nms_reg[b * kR + r];
        areaA[i] = (a[i].z - a[i].x) * (a[i].w - a[i].y);
        binter[i] = 0.f;   // all-zero IoUs -> argmax = 0 (first occurrence)
        bden[i]   = 1.f;
        bidx[i]   = 0;
    }

    // ---- IoU argmax over T GT boxes (division-free rational compare) ----
#pragma unroll 2
    for (int t = 0; t < kT; ++t) {
        float4 bb = s_box[t];
        float  ab = s_area[t];
#pragma unroll
        for (int i = 0; i < kIlp; i++) {
            float tt = fmaxf(a[i].x, bb.x);
            float ll = fmaxf(a[i].y, bb.y);
            float bo = fminf(a[i].z, bb.z);
            float rr = fminf(a[i].w, bb.w);
            float ih = fmaxf(bo - tt, 0.f);
            float iw = fmaxf(rr - ll, 0.f);
            float inter = ih * iw;
            float den = areaA[i] + ab - inter;   // > 0 always (areas > 0)
            // inter/den > binter/bden  <=>  inter*bden > binter*den
            bool upd = inter * bden[i] > binter[i] * den;
            binter[i] = upd ? inter : binter[i];
            bden[i]   = upd ? den   : bden[i];
            bidx[i]   = upd ? t     : bidx[i];
        }
    }

    // ---- per-thread loss contributions over masked proposals ----
    float cnt = 0.f, ce_s = 0.f, acc_s = 0.f, sl1_s = 0.f;
#pragma unroll
    for (int i = 0; i < kIlp; i++) {
        float iou = binter[i] / bden[i];       // IEEE div, matches reference rounding
        if (iou > kIouTh) {
            int r = chunk * kRPerBlock + i * kThreads + tid;
            cnt += 1.f;

            // Cross-entropy + argmax accuracy over C=81 logits
            const float* p = rcnn_cls + (size_t)(b * kR + r) * kC;
            float m = p[0];
            int am = 0;
            for (int c = 1; c < kC; ++c) {
                float v = p[c];
                if (v > m) { m = v; am = c; }  // strict > keeps first occurrence
            }
            float s = 0.f;
            for (int c = 0; c < kC; ++c) s += expf(p[c] - m);
            int label = s_cls[bidx[i]];
            ce_s += -(p[label] - m - logf(s));
            acc_s += (am == label) ? 1.f : 0.f;

            // Smooth-L1 regression vs stride-rounded offsets
            float4 gb = s_box[bidx[i]];
            float r0 = rintf(gb.x * 0.0625f) * 16.f;   // jnp.round = RN-to-even = rintf
            float r1 = rintf(gb.y * 0.0625f) * 16.f;
            float r2 = rintf(gb.z * 0.0625f) * 16.f;
            float r3 = rintf(gb.w * 0.0625f) * 16.f;
            float h = r2 - r0; h = (h == 0.f) ? 1.f : h;
            float w = r3 - r1; w = (w == 0.f) ? 1.f : w;
            float4 pr = rcnn_reg[b * kR + r];
            float t0 = (gb.x - r0) / h, t1 = (gb.y - r1) / w;
            float t2 = (gb.z - r2) / h, t3 = (gb.w - r3) / w;
            float d;
            d = fabsf(pr.x - t0); sl1_s += (d < 1.f) ? 0.5f * d * d : d - 0.5f;
            d = fabsf(pr.y - t1); sl1_s += (d < 1.f) ? 0.5f * d * d : d - 0.5f;
            d = fabsf(pr.z - t2); sl1_s += (d < 1.f) ? 0.5f * d * d : d - 0.5f;
            d = fabsf(pr.w - t3); sl1_s += (d < 1.f) ? 0.5f * d * d : d - 0.5f;
        }
    }

    // ---- deterministic block reduction ----
    __shared__ float s_red[kThreads / 32][4];
    cnt = warp_sum(cnt); ce_s = warp_sum(ce_s);
    acc_s = warp_sum(acc_s); sl1_s = warp_sum(sl1_s);
    int wid = tid >> 5, lid = tid & 31;
    if (lid == 0) {
        s_red[wid][0] = cnt; s_red[wid][1] = ce_s;
        s_red[wid][2] = acc_s; s_red[wid][3] = sl1_s;
    }
    __syncthreads();
    if (wid == 0) {
        const int nw = kThreads / 32;
        float v0 = (lid < nw) ? s_red[lid][0] : 0.f;
        float v1 = (lid < nw) ? s_red[lid][1] : 0.f;
        float v2 = (lid < nw) ? s_red[lid][2] : 0.f;
        float v3 = (lid < nw) ? s_red[lid][3] : 0.f;
        v0 = warp_sum(v0); v1 = warp_sum(v1); v2 = warp_sum(v2); v3 = warp_sum(v3);
        if (lid == 0) {
            g_partials[blockIdx.x][0] = v0;
            g_partials[blockIdx.x][1] = v1;
            g_partials[blockIdx.x][2] = v2;
            g_partials[blockIdx.x][3] = v3;
        }
    }
}

__global__ void rcnn_finalize(float* __restrict__ out) {
    const int tid = threadIdx.x;   // kNBlocks = 128 threads
    float v0 = g_partials[tid][0];
    float v1 = g_partials[tid][1];
    float v2 = g_partials[tid][2];
    float v3 = g_partials[tid][3];
    v0 = warp_sum(v0); v1 = warp_sum(v1); v2 = warp_sum(v2); v3 = warp_sum(v3);
    __shared__ float s[4][4];
    int wid = tid >> 5, lid = tid & 31;
    if (lid == 0) { s[wid][0] = v0; s[wid][1] = v1; s[wid][2] = v2; s[wid][3] = v3; }
    __syncthreads();
    if (tid == 0) {
        float npos = 0.f, ce = 0.f, acc = 0.f, sl1 = 0.f;
        for (int wgt = 0; wgt < 4; ++wgt) {
            npos += s[wgt][0]; ce += s[wgt][1]; acc += s[wgt][2]; sl1 += s[wgt][3];
        }
        float denom = fmaxf(npos, 1.f);
        bool has = npos > 0.f;
        out[0] = has ? ce / denom : 0.f;   // cls_loss
        out[1] = has ? sl1 / denom : 0.f;  // reg_loss (sum of per-coord means)
        out[2] = has ? acc / denom : 0.f;  // accuracy
    }
}

extern "C" void kernel_launch(void* const* d_in, const int* in_sizes, int n_in,
                              void* d_out, int out_size) {
    // metadata order: nms_reg, nms_cls (unused), rcnn_reg, rcnn_cls, bboxes, classes
    const float4* nms_reg  = (const float4*)d_in[0];
    const float4* rcnn_reg = (const float4*)d_in[2];
    const float*  rcnn_cls = (const float*)d_in[3];
    const float4* bboxes   = (const float4*)d_in[4];
    const int*    classes  = (const int*)d_in[5];
    (void)in_sizes; (void)n_in; (void)out_size;

    rcnn_main<<<kNBlocks, kThreads>>>(nms_reg, rcnn_reg, rcnn_cls, bboxes, classes);
    rcnn_finalize<<<1, kNBlocks>>>((float*)d_out);
}

// round 2
// speedup vs baseline: 1.1645x; 1.1645x over previous
#include <cuda_runtime.h>

// Problem constants (match reference module)
namespace {
constexpr int kB = 32, kT = 200, kR = 4096, kC = 81;
constexpr float kIouTh = 0.7f;
constexpr int kThreads = 512;                   // 16 warps -> 4 warps/SMSP
constexpr int kIlp = 2;
constexpr int kRPerBlock = kThreads * kIlp;     // 1024
constexpr int kBlocksPerB = kR / kRPerBlock;    // 4
constexpr int kNBlocks = kB * kBlocksPerB;      // 128
}

// Per-block partials: [npos, ce_sum, acc_sum, sl1_sum]
__device__ float g_partials[kNBlocks][4];
__device__ unsigned int g_done = 0;             // reset to 0 by last block each launch

__device__ __forceinline__ float warp_sum(float v) {
#pragma unroll
    for (int o = 16; o > 0; o >>= 1) v += __shfl_down_sync(0xffffffffu, v, o);
    return v;
}

__global__ __launch_bounds__(kThreads) void rcnn_main(
    const float4* __restrict__ nms_reg,   // [B,R,4]
    const float4* __restrict__ rcnn_reg,  // [B,R,4]
    const float*  __restrict__ rcnn_cls,  // [B,R,C]
    const float4* __restrict__ bboxes,    // [B,T,4]
    const int*    __restrict__ classes,   // [B,T]
    float* __restrict__ out)              // [3]
{
    __shared__ float4 s_box[kT];
    __shared__ float  s_area[kT];
    __shared__ int    s_cls[kT];

    const int b = blockIdx.x / kBlocksPerB;
    const int chunk = blockIdx.x % kBlocksPerB;
    const int tid = threadIdx.x;

    for (int i = tid; i < kT; i += kThreads) {
        float4 bb = bboxes[b * kT + i];
        s_box[i] = bb;
        s_area[i] = (bb.z - bb.x) * (bb.w - bb.y);
        s_cls[i] = classes[b * kT + i];
    }
    __syncthreads();

    float4 a[kIlp];
    float  areaA[kIlp];
    float  binter[kIlp], bden[kIlp];
    int    bidx[kIlp];

#pragma unroll
    for (int i = 0; i < kIlp; i++) {
        int r = chunk * kRPerBlock + i * kThreads + tid;   // coalesced
        a[i] = nms_reg[b * kR + r];
        areaA[i] = (a[i].z - a[i].x) * (a[i].w - a[i].y);
        binter[i] = 0.f;   // all-zero IoUs -> argmax = 0 (first occurrence)
        bden[i]   = 1.f;
        bidx[i]   = 0;
    }

    // ---- IoU argmax over T GT boxes (division-free rational compare) ----
#pragma unroll 4
    for (int t = 0; t < kT; ++t) {
        float4 bb = s_box[t];
        float  ab = s_area[t];
#pragma unroll
        for (int i = 0; i < kIlp; i++) {
            float tt = fmaxf(a[i].x, bb.x);
            float ll = fmaxf(a[i].y, bb.y);
            float bo = fminf(a[i].z, bb.z);
            float rr = fminf(a[i].w, bb.w);
            float ih = fmaxf(bo - tt, 0.f);
            float iw = fmaxf(rr - ll, 0.f);
            float inter = ih * iw;
            float den = areaA[i] + ab - inter;   // > 0 always (areas > 0)
            // inter/den > binter/bden  <=>  inter*bden > binter*den
            bool upd = inter * bden[i] > binter[i] * den;
            binter[i] = upd ? inter : binter[i];
            bden[i]   = upd ? den   : bden[i];
            bidx[i]   = upd ? t     : bidx[i];
        }
    }

    // ---- per-thread loss contributions over masked proposals ----
    float cnt = 0.f, ce_s = 0.f, acc_s = 0.f, sl1_s = 0.f;
#pragma unroll
    for (int i = 0; i < kIlp; i++) {
        float iou = binter[i] / bden[i];       // IEEE div, matches reference rounding
        if (iou > kIouTh) {
            int r = chunk * kRPerBlock + i * kThreads + tid;
            cnt += 1.f;

            // Cross-entropy + argmax accuracy over C=81 logits
            const float* p = rcnn_cls + (size_t)(b * kR + r) * kC;
            float m = p[0];
            int am = 0;
            for (int c = 1; c < kC; ++c) {
                float v = p[c];
                if (v > m) { m = v; am = c; }  // strict > keeps first occurrence
            }
            float s = 0.f;
            for (int c = 0; c < kC; ++c) s += expf(p[c] - m);
            int label = s_cls[bidx[i]];
            ce_s += -(p[label] - m - logf(s));
            acc_s += (am == label) ? 1.f : 0.f;

            // Smooth-L1 regression vs stride-rounded offsets
            float4 gb = s_box[bidx[i]];
            float r0 = rintf(gb.x * 0.0625f) * 16.f;   // jnp.round = RN-to-even = rintf
            float r1 = rintf(gb.y * 0.0625f) * 16.f;
            float r2 = rintf(gb.z * 0.0625f) * 16.f;
            float r3 = rintf(gb.w * 0.0625f) * 16.f;
            float h = r2 - r0; h = (h == 0.f) ? 1.f : h;
            float w = r3 - r1; w = (w == 0.f) ? 1.f : w;
            float4 pr = rcnn_reg[b * kR + r];
            float t0 = (gb.x - r0) / h, t1 = (gb.y - r1) / w;
            float t2 = (gb.z - r2) / h, t3 = (gb.w - r3) / w;
            float d;
            d = fabsf(pr.x - t0); sl1_s += (d < 1.f) ? 0.5f * d * d : d - 0.5f;
            d = fabsf(pr.y - t1); sl1_s += (d < 1.f) ? 0.5f * d * d : d - 0.5f;
            d = fabsf(pr.z - t2); sl1_s += (d < 1.f) ? 0.5f * d * d : d - 0.5f;
            d = fabsf(pr.w - t3); sl1_s += (d < 1.f) ? 0.5f * d * d : d - 0.5f;
        }
    }

    // ---- deterministic block reduction ----
    __shared__ float s_red[kThreads / 32][4];
    cnt = warp_sum(cnt); ce_s = warp_sum(ce_s);
    acc_s = warp_sum(acc_s); sl1_s = warp_sum(sl1_s);
    int wid = tid >> 5, lid = tid & 31;
    if (lid == 0) {
        s_red[wid][0] = cnt; s_red[wid][1] = ce_s;
        s_red[wid][2] = acc_s; s_red[wid][3] = sl1_s;
    }
    __syncthreads();
    if (wid == 0) {
        const int nw = kThreads / 32;
        float v0 = (lid < nw) ? s_red[lid][0] : 0.f;
        float v1 = (lid < nw) ? s_red[lid][1] : 0.f;
        float v2 = (lid < nw) ? s_red[lid][2] : 0.f;
        float v3 = (lid < nw) ? s_red[lid][3] : 0.f;
        v0 = warp_sum(v0); v1 = warp_sum(v1); v2 = warp_sum(v2); v3 = warp_sum(v3);
        if (lid == 0) {
            g_partials[blockIdx.x][0] = v0;
            g_partials[blockIdx.x][1] = v1;
            g_partials[blockIdx.x][2] = v2;
            g_partials[blockIdx.x][3] = v3;
        }
    }

    // ---- fused finalize: last block to finish reduces all partials ----
    __shared__ bool s_last;
    if (tid == 0) {
        __threadfence();
        unsigned int prev = atomicAdd(&g_done, 1u);
        s_last = (prev == (unsigned)(kNBlocks - 1));
    }
    __syncthreads();
    if (!s_last) return;

    // All 128 partials are visible (release fence before the final atomic,
    // __syncthreads orders every thread after tid 0's acquire; L1 holds no
    // stale copies since g_partials was not read earlier this launch).
    float v0 = 0.f, v1 = 0.f, v2 = 0.f, v3 = 0.f;
    if (tid < kNBlocks) {
        const volatile float* gp = &g_partials[tid][0];
        v0 = gp[0]; v1 = gp[1]; v2 = gp[2]; v3 = gp[3];
    }
    v0 = warp_sum(v0); v1 = warp_sum(v1); v2 = warp_sum(v2); v3 = warp_sum(v3);
    __shared__ float s_fin[kNBlocks / 32][4];
    if (lid == 0 && wid < kNBlocks / 32) {
        s_fin[wid][0] = v0; s_fin[wid][1] = v1; s_fin[wid][2] = v2; s_fin[wid][3] = v3;
    }
    __syncthreads();
    if (tid == 0) {
        float npos = 0.f, ce = 0.f, acc = 0.f, sl1 = 0.f;
        for (int k = 0; k < kNBlocks / 32; ++k) {
            npos += s_fin[k][0]; ce += s_fin[k][1]; acc += s_fin[k][2]; sl1 += s_fin[k][3];
        }
        float denom = fmaxf(npos, 1.f);
        bool has = npos > 0.f;
        out[0] = has ? ce / denom : 0.f;   // cls_loss
        out[1] = has ? sl1 / denom : 0.f;  // reg_loss (sum of per-coord means)
        out[2] = has ? acc / denom : 0.f;  // accuracy
        g_done = 0;                         // reset for next graph replay
    }
}

extern "C" void kernel_launch(void* const* d_in, const int* in_sizes, int n_in,
                              void* d_out, int out_size) {
    // metadata order: nms_reg, nms_cls (unused), rcnn_reg, rcnn_cls, bboxes, classes
    const float4* nms_reg  = (const float4*)d_in[0];
    const float4* rcnn_reg = (const float4*)d_in[2];
    const float*  rcnn_cls = (const float*)d_in[3];
    const float4* bboxes   = (const float4*)d_in[4];
    const int*    classes  = (const int*)d_in[5];
    (void)in_sizes; (void)n_in; (void)out_size;

    rcnn_main<<<kNBlocks, kThreads>>>(nms_reg, rcnn_reg, rcnn_cls, bboxes, classes,
                                      (float*)d_out);
}

// round 3
// speedup vs baseline: 1.2221x; 1.0495x over previous
#include <cuda_runtime.h>

// Problem constants (match reference module)
namespace {
constexpr int kB = 32, kT = 200, kR = 4096, kC = 81;
constexpr float kIouTh = 0.7f;
constexpr int kThreads = 256;                   // 8 warps/block
constexpr int kRPerBlock = kThreads;            // ILP = 1
constexpr int kBlocksPerB = kR / kRPerBlock;    // 16
constexpr int kNBlocks = kB * kBlocksPerB;      // 512 -> fully co-resident, ~28 warps/SM
}

// Per-block partials: [npos, ce_sum, acc_sum, sl1_sum]
__device__ float g_partials[kNBlocks][4];
__device__ unsigned int g_done = 0;             // reset to 0 by last block each launch

__device__ __forceinline__ float warp_sum(float v) {
#pragma unroll
    for (int o = 16; o > 0; o >>= 1) v += __shfl_down_sync(0xffffffffu, v, o);
    return v;
}

__global__ __launch_bounds__(kThreads) void rcnn_main(
    const float4* __restrict__ nms_reg,   // [B,R,4]
    const float4* __restrict__ rcnn_reg,  // [B,R,4]
    const float*  __restrict__ rcnn_cls,  // [B,R,C]
    const float4* __restrict__ bboxes,    // [B,T,4]
    const int*    __restrict__ classes,   // [B,T]
    float* __restrict__ out)              // [3]
{
    __shared__ float4 s_box[kT];
    __shared__ float  s_area[kT];
    __shared__ int    s_cls[kT];

    const int b = blockIdx.x / kBlocksPerB;
    const int chunk = blockIdx.x % kBlocksPerB;
    const int tid = threadIdx.x;

    for (int i = tid; i < kT; i += kThreads) {
        float4 bb = bboxes[b * kT + i];
        s_box[i] = bb;
        s_area[i] = (bb.z - bb.x) * (bb.w - bb.y);
        s_cls[i] = classes[b * kT + i];
    }
    __syncthreads();

    // Strided mapping: positives (r < T) are spread across all chunks so the
    // heavy softmax epilogue is load-balanced over the whole chip.
    const int r = chunk + kBlocksPerB * tid;

    const float4 a = nms_reg[b * kR + r];
    const float areaA = (a.z - a.x) * (a.w - a.y);
    float binter = 0.f;   // all-zero IoUs -> argmax = 0 (first occurrence)
    float bden   = 1.f;
    int   bidx   = 0;

    // ---- IoU argmax over T GT boxes (division-free rational compare) ----
    // One clamp dropped: if iw < 0 then inter <= 0 which can never win the
    // compare (binter >= 0, bden > 0, den > 0); any selected inter is > 0
    // hence both edges positive and the stored (inter, den) are exact.
#pragma unroll 4
    for (int t = 0; t < kT; ++t) {
        float4 bb = s_box[t];
        float  ab = s_area[t];
        float tt = fmaxf(a.x, bb.x);
        float ll = fmaxf(a.y, bb.y);
        float bo = fminf(a.z, bb.z);
        float rr = fminf(a.w, bb.w);
        float ih = fmaxf(bo - tt, 0.f);
        float iw = rr - ll;                  // unclamped (see note above)
        float inter = ih * iw;
        float den = areaA + ab - inter;      // > 0 always (areas > 0)
        // inter/den > binter/bden  <=>  inter*bden > binter*den
        bool upd = inter * bden > binter * den;
        binter = upd ? inter : binter;
        bden   = upd ? den   : bden;
        bidx   = upd ? t     : bidx;
    }

    // ---- per-thread loss contribution if positive ----
    float cnt = 0.f, ce_s = 0.f, acc_s = 0.f, sl1_s = 0.f;
    float iou = binter / bden;               // IEEE div, matches reference
    if (iou > kIouTh) {
        cnt = 1.f;

        // Cross-entropy + argmax accuracy over C=81 logits
        const float* p = rcnn_cls + (size_t)(b * kR + r) * kC;
        float m = p[0];
        int am = 0;
        for (int c = 1; c < kC; ++c) {
            float v = p[c];
            if (v > m) { m = v; am = c; }    // strict > keeps first occurrence
        }
        float s = 0.f;
        for (int c = 0; c < kC; ++c) s += expf(p[c] - m);
        int label = s_cls[bidx];
        ce_s = -(p[label] - m - logf(s));
        acc_s = (am == label) ? 1.f : 0.f;

        // Smooth-L1 regression vs stride-rounded offsets
        float4 gb = s_box[bidx];
        float r0 = rintf(gb.x * 0.0625f) * 16.f;   // jnp.round = RN-even = rintf
        float r1 = rintf(gb.y * 0.0625f) * 16.f;
        float r2 = rintf(gb.z * 0.0625f) * 16.f;
        float r3 = rintf(gb.w * 0.0625f) * 16.f;
        float h = r2 - r0; h = (h == 0.f) ? 1.f : h;
        float w = r3 - r1; w = (w == 0.f) ? 1.f : w;
        float4 pr = rcnn_reg[b * kR + r];
        float t0 = (gb.x - r0) / h, t1 = (gb.y - r1) / w;
        float t2 = (gb.z - r2) / h, t3 = (gb.w - r3) / w;
        float d;
        d = fabsf(pr.x - t0); sl1_s += (d < 1.f) ? 0.5f * d * d : d - 0.5f;
        d = fabsf(pr.y - t1); sl1_s += (d < 1.f) ? 0.5f * d * d : d - 0.5f;
        d = fabsf(pr.z - t2); sl1_s += (d < 1.f) ? 0.5f * d * d : d - 0.5f;
        d = fabsf(pr.w - t3); sl1_s += (d < 1.f) ? 0.5f * d * d : d - 0.5f;
    }

    // ---- deterministic block reduction ----
    __shared__ float s_red[kThreads / 32][4];
    cnt = warp_sum(cnt); ce_s = warp_sum(ce_s);
    acc_s = warp_sum(acc_s); sl1_s = warp_sum(sl1_s);
    int wid = tid >> 5, lid = tid & 31;
    if (lid == 0) {
        s_red[wid][0] = cnt; s_red[wid][1] = ce_s;
        s_red[wid][2] = acc_s; s_red[wid][3] = sl1_s;
    }
    __syncthreads();
    if (wid == 0) {
        const int nw = kThreads / 32;
        float v0 = (lid < nw) ? s_red[lid][0] : 0.f;
        float v1 = (lid < nw) ? s_red[lid][1] : 0.f;
        float v2 = (lid < nw) ? s_red[lid][2] : 0.f;
        float v3 = (lid < nw) ? s_red[lid][3] : 0.f;
        v0 = warp_sum(v0); v1 = warp_sum(v1); v2 = warp_sum(v2); v3 = warp_sum(v3);
        if (lid == 0) {
            g_partials[blockIdx.x][0] = v0;
            g_partials[blockIdx.x][1] = v1;
            g_partials[blockIdx.x][2] = v2;
            g_partials[blockIdx.x][3] = v3;
        }
    }

    // ---- fused finalize: last block to finish reduces all partials ----
    __shared__ bool s_last;
    if (tid == 0) {
        __threadfence();
        unsigned int prev = atomicAdd(&g_done, 1u);
        s_last = (prev == (unsigned)(kNBlocks - 1));
    }
    __syncthreads();
    if (!s_last) return;

    float v0 = 0.f, v1 = 0.f, v2 = 0.f, v3 = 0.f;
#pragma unroll
    for (int k = 0; k < kNBlocks / kThreads; ++k) {
        int idx = tid + k * kThreads;
        const volatile float* gp = &g_partials[idx][0];
        v0 += gp[0]; v1 += gp[1]; v2 += gp[2]; v3 += gp[3];
    }
    v0 = warp_sum(v0); v1 = warp_sum(v1); v2 = warp_sum(v2); v3 = warp_sum(v3);
    __shared__ float s_fin[kThreads / 32][4];
    if (lid == 0) {
        s_fin[wid][0] = v0; s_fin[wid][1] = v1; s_fin[wid][2] = v2; s_fin[wid][3] = v3;
    }
    __syncthreads();
    if (tid == 0) {
        float npos = 0.f, ce = 0.f, acc = 0.f, sl1 = 0.f;
        for (int k = 0; k < kThreads / 32; ++k) {
            npos += s_fin[k][0]; ce += s_fin[k][1]; acc += s_fin[k][2]; sl1 += s_fin[k][3];
        }
        float denom = fmaxf(npos, 1.f);
        bool has = npos > 0.f;
        out[0] = has ? ce / denom : 0.f;   // cls_loss
        out[1] = has ? sl1 / denom : 0.f;  // reg_loss (sum of per-coord means)
        out[2] = has ? acc / denom : 0.f;  // accuracy
        g_done = 0;                         // reset for next graph replay
    }
}

extern "C" void kernel_launch(void* const* d_in, const int* in_sizes, int n_in,
                              void* d_out, int out_size) {
    // metadata order: nms_reg, nms_cls (unused), rcnn_reg, rcnn_cls, bboxes, classes
    const float4* nms_reg  = (const float4*)d_in[0];
    const float4* rcnn_reg = (const float4*)d_in[2];
    const float*  rcnn_cls = (const float*)d_in[3];
    const float4* bboxes   = (const float4*)d_in[4];
    const int*    classes  = (const int*)d_in[5];
    (void)in_sizes; (void)n_in; (void)out_size;

    rcnn_main<<<kNBlocks, kThreads>>>(nms_reg, rcnn_reg, rcnn_cls, bboxes, classes,
                                      (float*)d_out);
}